// round 1
// baseline (speedup 1.0000x reference)
#include <cuda_runtime.h>

#define N_USERS 200000
#define N_ITEMS 100000
#define N_NODES 300000
#define N_EDGES 1500000
#define DIM 64
#define BERT 384

// Ping-pong scratch for layer activations (x_k). Static device globals — no allocs.
__device__ float g_buf[2][(size_t)N_NODES * DIM];

// ---------------------------------------------------------------------------
// Kernel 1: user init.  out[u] = user_emb[u] + gender_emb[g[u]] + age_emb[a[u]]
// Writes d_out (acc), g_buf[0] (x0), zeroes g_buf[1] (next y).
// One thread per float4 (16 threads per row).
// ---------------------------------------------------------------------------
__global__ void init_users_k(const float4* __restrict__ ue,
                             const float4* __restrict__ ge,
                             const float4* __restrict__ ae,
                             const int* __restrict__ ug,
                             const int* __restrict__ ua,
                             float4* __restrict__ out)
{
    int idx = blockIdx.x * blockDim.x + threadIdx.x;
    if (idx >= N_USERS * 16) return;
    int u = idx >> 4, s = idx & 15;
    int g = ug[u];
    int a = ua[u];
    float4 r = ue[idx];
    float4 gv = ge[g * 16 + s];
    float4 av = ae[a * 16 + s];
    r.x += gv.x + av.x; r.y += gv.y + av.y;
    r.z += gv.z + av.z; r.w += gv.w + av.w;
    out[idx] = r;
    reinterpret_cast<float4*>(g_buf[0])[idx] = r;
    reinterpret_cast<float4*>(g_buf[1])[idx] = make_float4(0.f, 0.f, 0.f, 0.f);
}

// ---------------------------------------------------------------------------
// Kernel 2: item init.  out[i] = item_bert[i] @ W^T + item_emb[i] + cat_emb[cat[i]]
// Tiled SGEMM: BM=64 rows, BN=64 (full N), BK=32, 128 threads, 8x4 reg tile.
// ---------------------------------------------------------------------------
#define GBM 64
#define GBK 32

__global__ __launch_bounds__(128) void item_gemm_k(
    const float* __restrict__ bert,      // [N_ITEMS, 384]
    const float* __restrict__ W,         // [64, 384]
    const float4* __restrict__ ie,       // item_emb as float4
    const float4* __restrict__ ce,       // cat_emb as float4
    const int* __restrict__ cat,
    float4* __restrict__ out)
{
    __shared__ __align__(16) float As[GBK][GBM + 4];
    __shared__ __align__(16) float Bs[GBK][64 + 4];

    int t  = threadIdx.x;
    int tx = t & 15;          // col group: cols tx*4 .. tx*4+3
    int ty = t >> 4;          // row group: rows ty*8 .. ty*8+7
    int rb = blockIdx.x * GBM;

    float acc[8][4];
#pragma unroll
    for (int j = 0; j < 8; j++)
#pragma unroll
        for (int c = 0; c < 4; c++) acc[j][c] = 0.f;

    for (int k0 = 0; k0 < BERT; k0 += GBK) {
        // Load A tile (64 rows x 32 k), transposed into As[k][m]
#pragma unroll
        for (int i = 0; i < 4; i++) {
            int q  = i * 128 + t;       // 0..511 float4 slots
            int m  = q >> 3;            // row within tile
            int kq = q & 7;             // float4 index within k-chunk
            float4 v = make_float4(0.f, 0.f, 0.f, 0.f);
            if (rb + m < N_ITEMS)
                v = *reinterpret_cast<const float4*>(
                        bert + (size_t)(rb + m) * BERT + k0 + kq * 4);
            As[kq * 4 + 0][m] = v.x;
            As[kq * 4 + 1][m] = v.y;
            As[kq * 4 + 2][m] = v.z;
            As[kq * 4 + 3][m] = v.w;
        }
        // Load B tile (64 cols x 32 k) from W[col][k], transposed into Bs[k][n]
#pragma unroll
        for (int i = 0; i < 4; i++) {
            int q  = i * 128 + t;
            int n  = q >> 3;
            int kq = q & 7;
            float4 v = *reinterpret_cast<const float4*>(
                           W + (size_t)n * BERT + k0 + kq * 4);
            Bs[kq * 4 + 0][n] = v.x;
            Bs[kq * 4 + 1][n] = v.y;
            Bs[kq * 4 + 2][n] = v.z;
            Bs[kq * 4 + 3][n] = v.w;
        }
        __syncthreads();

#pragma unroll
        for (int k = 0; k < GBK; k++) {
            float4 a0 = *reinterpret_cast<const float4*>(&As[k][ty * 8]);
            float4 a1 = *reinterpret_cast<const float4*>(&As[k][ty * 8 + 4]);
            float4 b  = *reinterpret_cast<const float4*>(&Bs[k][tx * 4]);
            float av[8] = {a0.x, a0.y, a0.z, a0.w, a1.x, a1.y, a1.z, a1.w};
            float bv[4] = {b.x, b.y, b.z, b.w};
#pragma unroll
            for (int j = 0; j < 8; j++)
#pragma unroll
                for (int c = 0; c < 4; c++)
                    acc[j][c] += av[j] * bv[c];
        }
        __syncthreads();
    }

    // Epilogue: + item_emb + cat_emb; write d_out, g_buf[0], zero g_buf[1]
#pragma unroll
    for (int j = 0; j < 8; j++) {
        int row = rb + ty * 8 + j;
        if (row < N_ITEMS) {
            int cc = cat[row];
            float4 e  = ie[row * 16 + tx];
            float4 cv = ce[cc * 16 + tx];
            float4 v = make_float4(acc[j][0] + e.x + cv.x,
                                   acc[j][1] + e.y + cv.y,
                                   acc[j][2] + e.z + cv.z,
                                   acc[j][3] + e.w + cv.w);
            size_t o = (size_t)(N_USERS + row) * 16 + tx;
            out[o] = v;
            reinterpret_cast<float4*>(g_buf[0])[o] = v;
            reinterpret_cast<float4*>(g_buf[1])[o] = make_float4(0.f, 0.f, 0.f, 0.f);
        }
    }
}

// ---------------------------------------------------------------------------
// Kernel 3: COO SpMM.  y[r] += val * x[c].  16 lanes per edge, float4 lanes,
// vector reduction (red.global.add.v4.f32, no return trip).
// xs selects which ping-pong buffer is x; the other is y (pre-zeroed).
// ---------------------------------------------------------------------------
__global__ __launch_bounds__(256) void spmm_k(int xs,
                                              const float* __restrict__ val,
                                              const int* __restrict__ rows,
                                              const int* __restrict__ cols)
{
    int tid = blockIdx.x * blockDim.x + threadIdx.x;
    int e = tid >> 4;
    if (e >= N_EDGES) return;
    int s = tid & 15;

    const float* __restrict__ x = g_buf[xs];
    float* __restrict__ y = g_buf[xs ^ 1];

    int r = __ldg(rows + e);
    int c = __ldg(cols + e);
    float v = __ldg(val + e);

    float4 xv = *reinterpret_cast<const float4*>(x + (size_t)c * DIM + s * 4);
    float* yp = y + (size_t)r * DIM + s * 4;
    asm volatile("red.global.add.v4.f32 [%0], {%1,%2,%3,%4};"
                 :: "l"(yp), "f"(xv.x * v), "f"(xv.y * v),
                    "f"(xv.z * v), "f"(xv.w * v)
                 : "memory");
}

// ---------------------------------------------------------------------------
// Kernel 4: acc += y, and zero the other buffer (prepares next layer's y).
// ys = index of buffer holding the layer output just produced.
// ---------------------------------------------------------------------------
__global__ void addacc_k(float4* __restrict__ acc, int ys)
{
    int i = blockIdx.x * blockDim.x + threadIdx.x;
    if (i >= N_NODES * 16) return;
    const float4* __restrict__ y = reinterpret_cast<const float4*>(g_buf[ys]);
    float4* __restrict__ z = reinterpret_cast<float4*>(g_buf[ys ^ 1]);
    float4 a = acc[i];
    float4 b = y[i];
    a.x += b.x; a.y += b.y; a.z += b.z; a.w += b.w;
    acc[i] = a;
    z[i] = make_float4(0.f, 0.f, 0.f, 0.f);
}

// ---------------------------------------------------------------------------
// Kernel 5: out = (acc + x3) * 0.25   (x3 lives in g_buf[1])
// ---------------------------------------------------------------------------
__global__ void final_k(float4* __restrict__ acc)
{
    int i = blockIdx.x * blockDim.x + threadIdx.x;
    if (i >= N_NODES * 16) return;
    const float4* __restrict__ y = reinterpret_cast<const float4*>(g_buf[1]);
    float4 a = acc[i];
    float4 b = y[i];
    a.x = (a.x + b.x) * 0.25f;
    a.y = (a.y + b.y) * 0.25f;
    a.z = (a.z + b.z) * 0.25f;
    a.w = (a.w + b.w) * 0.25f;
    acc[i] = a;
}

// ---------------------------------------------------------------------------
extern "C" void kernel_launch(void* const* d_in, const int* in_sizes, int n_in,
                              void* d_out, int out_size)
{
    const float* user_emb    = (const float*)d_in[0];
    const float* item_emb    = (const float*)d_in[1];
    const float* gender_emb  = (const float*)d_in[2];
    const float* age_emb     = (const float*)d_in[3];
    const float* cat_emb     = (const float*)d_in[4];
    const float* bert_proj_w = (const float*)d_in[5];
    const float* item_bert   = (const float*)d_in[6];
    const float* adj_val     = (const float*)d_in[7];
    const int*   user_gender = (const int*)d_in[8];
    const int*   user_age    = (const int*)d_in[9];
    const int*   item_cat    = (const int*)d_in[10];
    const int*   adj_row     = (const int*)d_in[11];
    const int*   adj_col     = (const int*)d_in[12];
    float4* out = (float4*)d_out;

    (void)in_sizes; (void)n_in; (void)out_size;

    // Init: acc = x0 in d_out, x0 in g_buf[0], g_buf[1] zeroed.
    init_users_k<<<(N_USERS * 16 + 255) / 256, 256>>>(
        (const float4*)user_emb, (const float4*)gender_emb,
        (const float4*)age_emb, user_gender, user_age, out);
    item_gemm_k<<<(N_ITEMS + GBM - 1) / GBM, 128>>>(
        item_bert, bert_proj_w, (const float4*)item_emb,
        (const float4*)cat_emb, item_cat, out);

    const int spmm_grid = (N_EDGES * 16 + 255) / 256;
    const int vec_grid  = (N_NODES * 16 + 255) / 256;

    // Layer 1: x0 (buf0) -> buf1; acc += buf1; zero buf0
    spmm_k<<<spmm_grid, 256>>>(0, adj_val, adj_row, adj_col);
    addacc_k<<<vec_grid, 256>>>(out, 1);
    // Layer 2: buf1 -> buf0; acc += buf0; zero buf1
    spmm_k<<<spmm_grid, 256>>>(1, adj_val, adj_row, adj_col);
    addacc_k<<<vec_grid, 256>>>(out, 0);
    // Layer 3: buf0 -> buf1; out = (acc + buf1) / 4
    spmm_k<<<spmm_grid, 256>>>(0, adj_val, adj_row, adj_col);
    final_k<<<vec_grid, 256>>>(out);
}

// round 2
// speedup vs baseline: 1.0132x; 1.0132x over previous
#include <cuda_runtime.h>

#define N_USERS 200000
#define N_ITEMS 100000
#define N_NODES 300000
#define N_EDGES 1500000
#define DIM 64
#define BERT 384

#define SCAN_B 1024
#define NB ((N_NODES + SCAN_B - 1) / SCAN_B)   // 293

// Scratch (static device globals — no allocs).
__device__ float g_buf[2][(size_t)N_NODES * DIM];      // x1, x2
__device__ int   g_cnt[N_NODES];                        // degree counts -> cursors
__device__ int   g_rowptr[N_NODES + 1];
__device__ int   g_blocksum[NB];
__device__ int   g_blockoff[NB];
__device__ int   g_csr_col[N_EDGES];
__device__ float g_csr_val[N_EDGES];

// ---------------------------------------------------------------------------
// CSR build: zero counts -> histogram -> 2-level exclusive scan -> scatter
// ---------------------------------------------------------------------------
__global__ void zero_cnt_k()
{
    int i = blockIdx.x * blockDim.x + threadIdx.x;
    if (i < N_NODES) g_cnt[i] = 0;
}

__global__ void hist_k(const int* __restrict__ rows)
{
    int e = blockIdx.x * blockDim.x + threadIdx.x;
    if (e < N_EDGES) atomicAdd(&g_cnt[rows[e]], 1);
}

__global__ __launch_bounds__(SCAN_B) void scan1_k()
{
    __shared__ int sh[SCAN_B];
    int i = blockIdx.x * SCAN_B + threadIdx.x;
    int v = (i < N_NODES) ? g_cnt[i] : 0;
    int orig = v;
    sh[threadIdx.x] = v;
    __syncthreads();
#pragma unroll
    for (int d = 1; d < SCAN_B; d <<= 1) {
        int t = (threadIdx.x >= d) ? sh[threadIdx.x - d] : 0;
        __syncthreads();
        sh[threadIdx.x] += t;
        __syncthreads();
    }
    if (i < N_NODES) g_rowptr[i] = sh[threadIdx.x] - orig;       // exclusive in-block
    if (threadIdx.x == SCAN_B - 1) g_blocksum[blockIdx.x] = sh[threadIdx.x];
}

__global__ __launch_bounds__(512) void scan2_k()
{
    __shared__ int sh[512];
    int t = threadIdx.x;
    int v = (t < NB) ? g_blocksum[t] : 0;
    int orig = v;
    sh[t] = v;
    __syncthreads();
#pragma unroll
    for (int d = 1; d < 512; d <<= 1) {
        int u = (t >= d) ? sh[t - d] : 0;
        __syncthreads();
        sh[t] += u;
        __syncthreads();
    }
    if (t < NB) g_blockoff[t] = sh[t] - orig;                    // exclusive
    if (t == 0) g_rowptr[N_NODES] = N_EDGES;
}

__global__ void scan3_k()
{
    int i = blockIdx.x * blockDim.x + threadIdx.x;
    if (i < N_NODES) {
        int r = g_rowptr[i] + g_blockoff[i >> 10];
        g_rowptr[i] = r;
        g_cnt[i] = r;                                            // cursor for scatter
    }
}

__global__ void scatter_k(const int* __restrict__ rows,
                          const int* __restrict__ cols,
                          const float* __restrict__ vals)
{
    int e = blockIdx.x * blockDim.x + threadIdx.x;
    if (e >= N_EDGES) return;
    int r = rows[e];
    int p = atomicAdd(&g_cnt[r], 1);
    g_csr_col[p] = cols[e];
    g_csr_val[p] = vals[e];
}

// ---------------------------------------------------------------------------
// User init: out[u] = user_emb[u] + gender_emb[g] + age_emb[a]
// ---------------------------------------------------------------------------
__global__ void init_users_k(const float4* __restrict__ ue,
                             const float4* __restrict__ ge,
                             const float4* __restrict__ ae,
                             const int* __restrict__ ug,
                             const int* __restrict__ ua,
                             float4* __restrict__ out)
{
    int idx = blockIdx.x * blockDim.x + threadIdx.x;
    if (idx >= N_USERS * 16) return;
    int u = idx >> 4, s = idx & 15;
    int g = ug[u];
    int a = ua[u];
    float4 r = ue[idx];
    float4 gv = ge[g * 16 + s];
    float4 av = ae[a * 16 + s];
    r.x += gv.x + av.x; r.y += gv.y + av.y;
    r.z += gv.z + av.z; r.w += gv.w + av.w;
    out[idx] = r;
}

// ---------------------------------------------------------------------------
// Item init GEMM with packed fp32 (fma.rn.f32x2): out[i] = bert[i] @ W^T + ...
// BM=64 rows, full N=64, BK=32, 128 threads; each thread: 8 rows x 4 cols.
// Accumulators packed along M (row pairs); B stored duplicated in smem so
// both FFMA2 operands arrive pre-packed from LDS.128.
// ---------------------------------------------------------------------------
#define GBM 64
#define GBK 32

#define FMA2(acc, a, b) \
    asm("fma.rn.f32x2 %0, %1, %2, %3;" : "=l"(acc) : "l"(a), "l"(b), "l"(acc))

__device__ __forceinline__ float2 unpack2(unsigned long long u)
{
    float2 f;
    asm("mov.b64 {%0, %1}, %2;" : "=f"(f.x), "=f"(f.y) : "l"(u));
    return f;
}

__global__ __launch_bounds__(128) void item_gemm_k(
    const float* __restrict__ bert,      // [N_ITEMS, 384]
    const float* __restrict__ W,         // [64, 384]
    const float4* __restrict__ ie,
    const float4* __restrict__ ce,
    const int* __restrict__ cat,
    float4* __restrict__ out)
{
    __shared__ __align__(16) float As[GBK][GBM + 4];     // [k][m]
    __shared__ __align__(16) float Bs[GBK][136];         // [k][2n] duplicated

    int t  = threadIdx.x;
    int tx = t & 15;          // col group: cols tx*4 .. tx*4+3
    int ty = t >> 4;          // row group: rows ty*8 .. ty*8+7
    int rb = blockIdx.x * GBM;

    unsigned long long acc2[4][4];       // [row-pair][col], each {even,odd}
#pragma unroll
    for (int p = 0; p < 4; p++)
#pragma unroll
        for (int c = 0; c < 4; c++) acc2[p][c] = 0ull;

    for (int k0 = 0; k0 < BERT; k0 += GBK) {
        // A tile: 64 rows x 32 k, transposed to As[k][m]
#pragma unroll
        for (int i = 0; i < 4; i++) {
            int q  = i * 128 + t;
            int m  = q >> 3;
            int kq = q & 7;
            float4 v = make_float4(0.f, 0.f, 0.f, 0.f);
            if (rb + m < N_ITEMS)
                v = *reinterpret_cast<const float4*>(
                        bert + (size_t)(rb + m) * BERT + k0 + kq * 4);
            As[kq * 4 + 0][m] = v.x;
            As[kq * 4 + 1][m] = v.y;
            As[kq * 4 + 2][m] = v.z;
            As[kq * 4 + 3][m] = v.w;
        }
        // B tile: W[n][k], duplicated along n: Bs[k][2n] = Bs[k][2n+1] = W[n][k]
#pragma unroll
        for (int i = 0; i < 4; i++) {
            int q  = i * 128 + t;
            int n  = q >> 3;
            int kq = q & 7;
            float4 v = *reinterpret_cast<const float4*>(
                           W + (size_t)n * BERT + k0 + kq * 4);
            Bs[kq * 4 + 0][2 * n] = v.x; Bs[kq * 4 + 0][2 * n + 1] = v.x;
            Bs[kq * 4 + 1][2 * n] = v.y; Bs[kq * 4 + 1][2 * n + 1] = v.y;
            Bs[kq * 4 + 2][2 * n] = v.z; Bs[kq * 4 + 2][2 * n + 1] = v.z;
            Bs[kq * 4 + 3][2 * n] = v.w; Bs[kq * 4 + 3][2 * n + 1] = v.w;
        }
        __syncthreads();

#pragma unroll
        for (int k = 0; k < GBK; k++) {
            // row pairs: {m0,m1},{m2,m3},{m4,m5},{m6,m7}
            ulonglong2 a0 = *reinterpret_cast<const ulonglong2*>(&As[k][ty * 8]);
            ulonglong2 a1 = *reinterpret_cast<const ulonglong2*>(&As[k][ty * 8 + 4]);
            // duplicated cols: {b0,b0},{b1,b1},{b2,b2},{b3,b3}
            ulonglong2 b0 = *reinterpret_cast<const ulonglong2*>(&Bs[k][tx * 8]);
            ulonglong2 b1 = *reinterpret_cast<const ulonglong2*>(&Bs[k][tx * 8 + 4]);
            unsigned long long ap[4] = {a0.x, a0.y, a1.x, a1.y};
            unsigned long long bp[4] = {b0.x, b0.y, b1.x, b1.y};
#pragma unroll
            for (int p = 0; p < 4; p++)
#pragma unroll
                for (int c = 0; c < 4; c++)
                    FMA2(acc2[p][c], ap[p], bp[c]);
        }
        __syncthreads();
    }

    // Epilogue: + item_emb + cat_emb
#pragma unroll
    for (int p = 0; p < 4; p++) {
        float2 c0 = unpack2(acc2[p][0]);
        float2 c1 = unpack2(acc2[p][1]);
        float2 c2 = unpack2(acc2[p][2]);
        float2 c3 = unpack2(acc2[p][3]);
        int r0 = rb + ty * 8 + 2 * p;
#pragma unroll
        for (int h = 0; h < 2; h++) {
            int row = r0 + h;
            if (row < N_ITEMS) {
                int cc = cat[row];
                float4 e  = ie[row * 16 + tx];
                float4 cv = ce[cc * 16 + tx];
                float4 v;
                v.x = (h ? c0.y : c0.x) + e.x + cv.x;
                v.y = (h ? c1.y : c1.x) + e.y + cv.y;
                v.z = (h ? c2.y : c2.x) + e.z + cv.z;
                v.w = (h ? c3.y : c3.x) + e.w + cv.w;
                out[(size_t)(N_USERS + row) * 16 + tx] = v;
            }
        }
    }
}

// ---------------------------------------------------------------------------
// CSR gather SpMM: y[r] = sum_j val[j] * x[col[j]].  16 lanes per row
// (one float4 segment each); edges broadcast via shfl within the 16-group.
// No atomics, no pre-zeroing.
// ---------------------------------------------------------------------------
__device__ __forceinline__ float4 spmm_row(const float4* __restrict__ x,
                                           int r, int s, unsigned mask)
{
    int beg = __ldg(&g_rowptr[r]);
    int end = __ldg(&g_rowptr[r + 1]);
    float4 acc = make_float4(0.f, 0.f, 0.f, 0.f);
    for (int j0 = beg; j0 < end; j0 += 16) {
        int jj = j0 + s;
        int c = 0; float v = 0.f;
        if (jj < end) { c = __ldg(&g_csr_col[jj]); v = __ldg(&g_csr_val[jj]); }
        int n = min(16, end - j0);
        for (int t = 0; t < n; t++) {
            int   cb = __shfl_sync(mask, c, t, 16);
            float vb = __shfl_sync(mask, v, t, 16);
            float4 xv = x[cb * 16 + s];
            acc.x += vb * xv.x; acc.y += vb * xv.y;
            acc.z += vb * xv.z; acc.w += vb * xv.w;
        }
    }
    return acc;
}

__global__ __launch_bounds__(256) void spmm_gather_k(const float4* __restrict__ x,
                                                     float4* __restrict__ y)
{
    int tid = blockIdx.x * blockDim.x + threadIdx.x;
    int r = tid >> 4;
    if (r >= N_NODES) return;
    int s = tid & 15;
    unsigned mask = 0xFFFFu << (threadIdx.x & 16);
    y[r * 16 + s] = spmm_row(x, r, s, mask);
}

// Last layer fused with the mean: out = (x0 + x1 + x2 + A*x2) / 4
__global__ __launch_bounds__(256) void spmm_final_k(const float4* __restrict__ x,  // x2
                                                    const float4* __restrict__ b1, // x1
                                                    float4* __restrict__ out)      // x0 in, result out
{
    int tid = blockIdx.x * blockDim.x + threadIdx.x;
    int r = tid >> 4;
    if (r >= N_NODES) return;
    int s = tid & 15;
    unsigned mask = 0xFFFFu << (threadIdx.x & 16);
    float4 acc = spmm_row(x, r, s, mask);
    int o = r * 16 + s;
    float4 a0 = out[o];
    float4 a1 = b1[o];
    float4 a2 = x[o];
    float4 v;
    v.x = (a0.x + a1.x + a2.x + acc.x) * 0.25f;
    v.y = (a0.y + a1.y + a2.y + acc.y) * 0.25f;
    v.z = (a0.z + a1.z + a2.z + acc.z) * 0.25f;
    v.w = (a0.w + a1.w + a2.w + acc.w) * 0.25f;
    out[o] = v;
}

// ---------------------------------------------------------------------------
extern "C" void kernel_launch(void* const* d_in, const int* in_sizes, int n_in,
                              void* d_out, int out_size)
{
    const float* user_emb    = (const float*)d_in[0];
    const float* item_emb    = (const float*)d_in[1];
    const float* gender_emb  = (const float*)d_in[2];
    const float* age_emb     = (const float*)d_in[3];
    const float* cat_emb     = (const float*)d_in[4];
    const float* bert_proj_w = (const float*)d_in[5];
    const float* item_bert   = (const float*)d_in[6];
    const float* adj_val     = (const float*)d_in[7];
    const int*   user_gender = (const int*)d_in[8];
    const int*   user_age    = (const int*)d_in[9];
    const int*   item_cat    = (const int*)d_in[10];
    const int*   adj_row     = (const int*)d_in[11];
    const int*   adj_col     = (const int*)d_in[12];
    float4* out = (float4*)d_out;

    (void)in_sizes; (void)n_in; (void)out_size;

    float4* buf0; cudaGetSymbolAddress((void**)&buf0, g_buf);      // x1
    float4* buf1 = buf0 + (size_t)N_NODES * 16;                    // x2

    const int eg = (N_EDGES + 255) / 256;
    const int ng = (N_NODES + 255) / 256;

    // CSR build
    zero_cnt_k<<<ng, 256>>>();
    hist_k<<<eg, 256>>>(adj_row);
    scan1_k<<<NB, SCAN_B>>>();
    scan2_k<<<1, 512>>>();
    scan3_k<<<ng, 256>>>();
    scatter_k<<<eg, 256>>>(adj_row, adj_col, adj_val);

    // Init x0 directly into d_out
    init_users_k<<<(N_USERS * 16 + 255) / 256, 256>>>(
        (const float4*)user_emb, (const float4*)gender_emb,
        (const float4*)age_emb, user_gender, user_age, out);
    item_gemm_k<<<(N_ITEMS + GBM - 1) / GBM, 128>>>(
        item_bert, bert_proj_w, (const float4*)item_emb,
        (const float4*)cat_emb, item_cat, out);

    const int sg = (N_NODES * 16 + 255) / 256;
    spmm_gather_k<<<sg, 256>>>(out,  buf0);          // x1 = A x0
    spmm_gather_k<<<sg, 256>>>(buf0, buf1);          // x2 = A x1
    spmm_final_k<<<sg, 256>>>(buf1, buf0, out);      // out = (x0+x1+x2+A x2)/4
}

// round 3
// speedup vs baseline: 1.4291x; 1.4105x over previous
#include <cuda_runtime.h>

#define N_USERS 200000
#define N_ITEMS 100000
#define N_NODES 300000
#define N_EDGES 1500000
#define DIM 64
#define BERT 384

#define SCAN_B 1024
#define NB ((N_NODES + SCAN_B - 1) / SCAN_B)   // 293

// Scratch (static device globals — no allocs).
__device__ float g_buf[2][(size_t)N_NODES * DIM];      // x1, x2
__device__ int   g_cnt[N_NODES];                        // degree counts -> cursors
__device__ int   g_rowptr[N_NODES + 1];
__device__ int   g_blocksum[NB];
__device__ int   g_blockoff[NB];
__device__ __align__(16) int2 g_edge[N_EDGES];          // {col, val bits}

// ---------------------------------------------------------------------------
// CSR build: zero counts -> histogram -> 2-level exclusive scan -> scatter
// ---------------------------------------------------------------------------
__global__ void zero_cnt_k()
{
    int i = blockIdx.x * blockDim.x + threadIdx.x;
    if (i < N_NODES) g_cnt[i] = 0;
}

__global__ void hist_k(const int* __restrict__ rows)
{
    int e = blockIdx.x * blockDim.x + threadIdx.x;
    if (e < N_EDGES) atomicAdd(&g_cnt[rows[e]], 1);
}

__global__ __launch_bounds__(SCAN_B) void scan1_k()
{
    __shared__ int sh[SCAN_B];
    int i = blockIdx.x * SCAN_B + threadIdx.x;
    int v = (i < N_NODES) ? g_cnt[i] : 0;
    int orig = v;
    sh[threadIdx.x] = v;
    __syncthreads();
#pragma unroll
    for (int d = 1; d < SCAN_B; d <<= 1) {
        int t = (threadIdx.x >= d) ? sh[threadIdx.x - d] : 0;
        __syncthreads();
        sh[threadIdx.x] += t;
        __syncthreads();
    }
    if (i < N_NODES) g_rowptr[i] = sh[threadIdx.x] - orig;       // exclusive in-block
    if (threadIdx.x == SCAN_B - 1) g_blocksum[blockIdx.x] = sh[threadIdx.x];
}

__global__ __launch_bounds__(512) void scan2_k()
{
    __shared__ int sh[512];
    int t = threadIdx.x;
    int v = (t < NB) ? g_blocksum[t] : 0;
    int orig = v;
    sh[t] = v;
    __syncthreads();
#pragma unroll
    for (int d = 1; d < 512; d <<= 1) {
        int u = (t >= d) ? sh[t - d] : 0;
        __syncthreads();
        sh[t] += u;
        __syncthreads();
    }
    if (t < NB) g_blockoff[t] = sh[t] - orig;                    // exclusive
    if (t == 0) g_rowptr[N_NODES] = N_EDGES;
}

__global__ void scan3_k()
{
    int i = blockIdx.x * blockDim.x + threadIdx.x;
    if (i < N_NODES) {
        int r = g_rowptr[i] + g_blockoff[i >> 10];
        g_rowptr[i] = r;
        g_cnt[i] = r;                                            // cursor for scatter
    }
}

__global__ void scatter_k(const int* __restrict__ rows,
                          const int* __restrict__ cols,
                          const float* __restrict__ vals)
{
    int e = blockIdx.x * blockDim.x + threadIdx.x;
    if (e >= N_EDGES) return;
    int r = rows[e];
    int p = atomicAdd(&g_cnt[r], 1);
    g_edge[p] = make_int2(cols[e], __float_as_int(vals[e]));
}

// ---------------------------------------------------------------------------
// User init: out[u] = user_emb[u] + gender_emb[g] + age_emb[a]
// ---------------------------------------------------------------------------
__global__ void init_users_k(const float4* __restrict__ ue,
                             const float4* __restrict__ ge,
                             const float4* __restrict__ ae,
                             const int* __restrict__ ug,
                             const int* __restrict__ ua,
                             float4* __restrict__ out)
{
    int idx = blockIdx.x * blockDim.x + threadIdx.x;
    if (idx >= N_USERS * 16) return;
    int u = idx >> 4, s = idx & 15;
    int g = ug[u];
    int a = ua[u];
    float4 r = ue[idx];
    float4 gv = ge[g * 16 + s];
    float4 av = ae[a * 16 + s];
    r.x += gv.x + av.x; r.y += gv.y + av.y;
    r.z += gv.z + av.z; r.w += gv.w + av.w;
    out[idx] = r;
}

// ---------------------------------------------------------------------------
// Item init GEMM, fp32 packed (fma.rn.f32x2).
// BM=128 rows x BN=64 cols (full), BK=32, 128 threads, 8x8 per-thread tile.
// Accumulators packed along M (row pairs); B duplicated into packed regs via
// mov.b64 {b,b} (ALU pipe, overlaps FMA).
// ---------------------------------------------------------------------------
#define GBM 128
#define GBK 32

#define FMA2(acc, a, b) \
    asm("fma.rn.f32x2 %0, %1, %2, %3;" : "=l"(acc) : "l"(a), "l"(b), "l"(acc))
#define PACK2(u, f) \
    asm("mov.b64 %0, {%1, %1};" : "=l"(u) : "f"(f))

__device__ __forceinline__ float2 unpack2(unsigned long long u)
{
    float2 f;
    asm("mov.b64 {%0, %1}, %2;" : "=f"(f.x), "=f"(f.y) : "l"(u));
    return f;
}

__global__ __launch_bounds__(128) void item_gemm_k(
    const float* __restrict__ bert,      // [N_ITEMS, 384]
    const float* __restrict__ W,         // [64, 384]
    const float4* __restrict__ ie,
    const float4* __restrict__ ce,
    const int* __restrict__ cat,
    float4* __restrict__ out)
{
    __shared__ __align__(16) float As[GBK][GBM + 4];   // [k][m]  32x132
    __shared__ __align__(16) float Bs[GBK][64 + 4];    // [k][n]  32x68

    int t  = threadIdx.x;
    int tx = t & 7;           // col group: cols tx*8 .. tx*8+7
    int ty = t >> 3;          // row group: rows ty*8 .. ty*8+7
    int rb = blockIdx.x * GBM;

    unsigned long long acc2[4][8];       // [row-pair][col]
#pragma unroll
    for (int p = 0; p < 4; p++)
#pragma unroll
        for (int c = 0; c < 8; c++) acc2[p][c] = 0ull;

    for (int k0 = 0; k0 < BERT; k0 += GBK) {
        // A tile: 128 rows x 32 k -> As[k][m]
#pragma unroll
        for (int i = 0; i < 8; i++) {
            int q  = i * 128 + t;
            int m  = q >> 3;
            int kq = q & 7;
            float4 v = make_float4(0.f, 0.f, 0.f, 0.f);
            if (rb + m < N_ITEMS)
                v = *reinterpret_cast<const float4*>(
                        bert + (size_t)(rb + m) * BERT + k0 + kq * 4);
            As[kq * 4 + 0][m] = v.x;
            As[kq * 4 + 1][m] = v.y;
            As[kq * 4 + 2][m] = v.z;
            As[kq * 4 + 3][m] = v.w;
        }
        // B tile: W[n][k] -> Bs[k][n]
#pragma unroll
        for (int i = 0; i < 4; i++) {
            int q  = i * 128 + t;
            int n  = q >> 3;
            int kq = q & 7;
            float4 v = *reinterpret_cast<const float4*>(
                           W + (size_t)n * BERT + k0 + kq * 4);
            Bs[kq * 4 + 0][n] = v.x;
            Bs[kq * 4 + 1][n] = v.y;
            Bs[kq * 4 + 2][n] = v.z;
            Bs[kq * 4 + 3][n] = v.w;
        }
        __syncthreads();

#pragma unroll
        for (int k = 0; k < GBK; k++) {
            ulonglong2 a0 = *reinterpret_cast<const ulonglong2*>(&As[k][ty * 8]);
            ulonglong2 a1 = *reinterpret_cast<const ulonglong2*>(&As[k][ty * 8 + 4]);
            float4 b0 = *reinterpret_cast<const float4*>(&Bs[k][tx * 8]);
            float4 b1 = *reinterpret_cast<const float4*>(&Bs[k][tx * 8 + 4]);
            unsigned long long ap[4] = {a0.x, a0.y, a1.x, a1.y};
            unsigned long long bp[8];
            PACK2(bp[0], b0.x); PACK2(bp[1], b0.y);
            PACK2(bp[2], b0.z); PACK2(bp[3], b0.w);
            PACK2(bp[4], b1.x); PACK2(bp[5], b1.y);
            PACK2(bp[6], b1.z); PACK2(bp[7], b1.w);
#pragma unroll
            for (int p = 0; p < 4; p++)
#pragma unroll
                for (int c = 0; c < 8; c++)
                    FMA2(acc2[p][c], ap[p], bp[c]);
        }
        __syncthreads();
    }

    // Epilogue: + item_emb + cat_emb.  Thread owns rows rb+ty*8+{0..7},
    // cols tx*8..tx*8+7 -> float4 segments 2tx and 2tx+1.
#pragma unroll
    for (int p = 0; p < 4; p++) {
        float2 c0 = unpack2(acc2[p][0]);
        float2 c1 = unpack2(acc2[p][1]);
        float2 c2 = unpack2(acc2[p][2]);
        float2 c3 = unpack2(acc2[p][3]);
        float2 c4 = unpack2(acc2[p][4]);
        float2 c5 = unpack2(acc2[p][5]);
        float2 c6 = unpack2(acc2[p][6]);
        float2 c7 = unpack2(acc2[p][7]);
        int r0 = rb + ty * 8 + 2 * p;
#pragma unroll
        for (int h = 0; h < 2; h++) {
            int row = r0 + h;
            if (row < N_ITEMS) {
                int cc = cat[row];
                int s0 = tx * 2, s1 = tx * 2 + 1;
                float4 e0 = ie[row * 16 + s0];
                float4 e1 = ie[row * 16 + s1];
                float4 v0 = ce[cc * 16 + s0];
                float4 v1 = ce[cc * 16 + s1];
                float4 o0, o1;
                o0.x = (h ? c0.y : c0.x) + e0.x + v0.x;
                o0.y = (h ? c1.y : c1.x) + e0.y + v0.y;
                o0.z = (h ? c2.y : c2.x) + e0.z + v0.z;
                o0.w = (h ? c3.y : c3.x) + e0.w + v0.w;
                o1.x = (h ? c4.y : c4.x) + e1.x + v1.x;
                o1.y = (h ? c5.y : c5.x) + e1.y + v1.y;
                o1.z = (h ? c6.y : c6.x) + e1.z + v1.z;
                o1.w = (h ? c7.y : c7.x) + e1.w + v1.w;
                size_t ob = (size_t)(N_USERS + row) * 16;
                out[ob + s0] = o0;
                out[ob + s1] = o1;
            }
        }
    }
}

// ---------------------------------------------------------------------------
// CSR gather SpMM: y[r] = sum_j val[j] * x[col[j]].  16 lanes per row,
// one float4 segment each.  All 16 lanes load the same edge record
// (same-address broadcast, L1-resident).  Unroll x4 for MLP on x-row loads.
// ---------------------------------------------------------------------------
__device__ __forceinline__ float4 spmm_row(const float4* __restrict__ x,
                                           int r, int s)
{
    int beg = __ldg(&g_rowptr[r]);
    int end = __ldg(&g_rowptr[r + 1]);
    float4 acc = make_float4(0.f, 0.f, 0.f, 0.f);
    int jj = beg;
    for (; jj + 4 <= end; jj += 4) {
        int2 e0 = __ldg(&g_edge[jj + 0]);
        int2 e1 = __ldg(&g_edge[jj + 1]);
        int2 e2 = __ldg(&g_edge[jj + 2]);
        int2 e3 = __ldg(&g_edge[jj + 3]);
        float4 x0 = __ldg(&x[e0.x * 16 + s]);
        float4 x1 = __ldg(&x[e1.x * 16 + s]);
        float4 x2 = __ldg(&x[e2.x * 16 + s]);
        float4 x3 = __ldg(&x[e3.x * 16 + s]);
        float v0 = __int_as_float(e0.y);
        float v1 = __int_as_float(e1.y);
        float v2 = __int_as_float(e2.y);
        float v3 = __int_as_float(e3.y);
        acc.x += v0 * x0.x; acc.y += v0 * x0.y; acc.z += v0 * x0.z; acc.w += v0 * x0.w;
        acc.x += v1 * x1.x; acc.y += v1 * x1.y; acc.z += v1 * x1.z; acc.w += v1 * x1.w;
        acc.x += v2 * x2.x; acc.y += v2 * x2.y; acc.z += v2 * x2.z; acc.w += v2 * x2.w;
        acc.x += v3 * x3.x; acc.y += v3 * x3.y; acc.z += v3 * x3.z; acc.w += v3 * x3.w;
    }
    for (; jj < end; jj++) {
        int2 e = __ldg(&g_edge[jj]);
        float4 xv = __ldg(&x[e.x * 16 + s]);
        float v = __int_as_float(e.y);
        acc.x += v * xv.x; acc.y += v * xv.y;
        acc.z += v * xv.z; acc.w += v * xv.w;
    }
    return acc;
}

__global__ __launch_bounds__(256) void spmm_gather_k(const float4* __restrict__ x,
                                                     float4* __restrict__ y)
{
    int tid = blockIdx.x * blockDim.x + threadIdx.x;
    int r = tid >> 4;
    if (r >= N_NODES) return;
    int s = tid & 15;
    y[r * 16 + s] = spmm_row(x, r, s);
}

// Last layer fused with the mean: out = (x0 + x1 + x2 + A*x2) / 4
__global__ __launch_bounds__(256) void spmm_final_k(const float4* __restrict__ x,  // x2
                                                    const float4* __restrict__ b1, // x1
                                                    float4* __restrict__ out)      // x0 in, result out
{
    int tid = blockIdx.x * blockDim.x + threadIdx.x;
    int r = tid >> 4;
    if (r >= N_NODES) return;
    int s = tid & 15;
    float4 acc = spmm_row(x, r, s);
    int o = r * 16 + s;
    float4 a0 = out[o];
    float4 a1 = b1[o];
    float4 a2 = x[o];
    float4 v;
    v.x = (a0.x + a1.x + a2.x + acc.x) * 0.25f;
    v.y = (a0.y + a1.y + a2.y + acc.y) * 0.25f;
    v.z = (a0.z + a1.z + a2.z + acc.z) * 0.25f;
    v.w = (a0.w + a1.w + a2.w + acc.w) * 0.25f;
    out[o] = v;
}

// ---------------------------------------------------------------------------
extern "C" void kernel_launch(void* const* d_in, const int* in_sizes, int n_in,
                              void* d_out, int out_size)
{
    const float* user_emb    = (const float*)d_in[0];
    const float* item_emb    = (const float*)d_in[1];
    const float* gender_emb  = (const float*)d_in[2];
    const float* age_emb     = (const float*)d_in[3];
    const float* cat_emb     = (const float*)d_in[4];
    const float* bert_proj_w = (const float*)d_in[5];
    const float* item_bert   = (const float*)d_in[6];
    const float* adj_val     = (const float*)d_in[7];
    const int*   user_gender = (const int*)d_in[8];
    const int*   user_age    = (const int*)d_in[9];
    const int*   item_cat    = (const int*)d_in[10];
    const int*   adj_row     = (const int*)d_in[11];
    const int*   adj_col     = (const int*)d_in[12];
    float4* out = (float4*)d_out;

    (void)in_sizes; (void)n_in; (void)out_size;

    float4* buf0; cudaGetSymbolAddress((void**)&buf0, g_buf);      // x1
    float4* buf1 = buf0 + (size_t)N_NODES * 16;                    // x2

    const int eg = (N_EDGES + 255) / 256;
    const int ng = (N_NODES + 255) / 256;

    // CSR build, with item_gemm placed at launch index 3 (ncu profiles it).
    zero_cnt_k<<<ng, 256>>>();                                     // 0
    hist_k<<<eg, 256>>>(adj_row);                                  // 1
    scan1_k<<<NB, SCAN_B>>>();                                     // 2
    item_gemm_k<<<(N_ITEMS + GBM - 1) / GBM, 128>>>(               // 3 <- profiled
        item_bert, bert_proj_w, (const float4*)item_emb,
        (const float4*)cat_emb, item_cat, out);
    scan2_k<<<1, 512>>>();                                         // 4
    scan3_k<<<ng, 256>>>();                                        // 5
    scatter_k<<<eg, 256>>>(adj_row, adj_col, adj_val);             // 6
    init_users_k<<<(N_USERS * 16 + 255) / 256, 256>>>(             // 7
        (const float4*)user_emb, (const float4*)gender_emb,
        (const float4*)age_emb, user_gender, user_age, out);

    const int sg = (N_NODES * 16 + 255) / 256;
    spmm_gather_k<<<sg, 256>>>(out,  buf0);          // x1 = A x0
    spmm_gather_k<<<sg, 256>>>(buf0, buf1);          // x2 = A x1
    spmm_final_k<<<sg, 256>>>(buf1, buf0, out);      // out = (x0+x1+x2+A x2)/4
}